// round 6
// baseline (speedup 1.0000x reference)
#include <cuda_runtime.h>
#include <math.h>

#define NB   64
#define IMG  384
#define CIN  3
#define PS   16
#define DM   96
#define DS   16
#define DI   96
#define HP   24
#define NT   576
#define NR   (NB*NT)          // 36864 token rows
#define NPIX (NB*CIN*IMG*IMG) // 28311552

// ---------------- scratch (device globals; no allocs allowed) ----------------
static __device__ float  g_xl[NPIX];        // preprocessed image, PATCH-MAJOR [gp][768]
static __device__ float  g_WpeT[768*96];    // transposed patch weights [k][d]
static __device__ float  g_tokens[NR*DM];
static __device__ float  g_vis[NR];
static __device__ float  g_gate[NR*DM];
static __device__ float  g_xin[NR*DI];      // pre-conv x branch
static __device__ float  g_zg[NR*DI];       // silu(z)*vis
static __device__ float  g_bc[NR*32];       // B(16) | C(16)
static __device__ float4 g_meta[NR*DI];     // {dt, dt*xs, D*xs*zg, zg}
static __device__ float  g_yg[NR*DI];

__device__ __forceinline__ float sigm_(float x){ return 1.f/(1.f+__expf(-x)); }
__device__ __forceinline__ float silu_(float x){ return x/(1.f+__expf(-x)); }
__device__ __forceinline__ float softplus_(float x){ return (x>20.f)? x : __logf(1.f+__expf(x)); }

// ---- packed fp32x2 helpers (Blackwell FFMA2 path, PTX-only) ----
typedef unsigned long long u64;
__device__ __forceinline__ void ffma2(u64 &d, u64 a, u64 b){
    asm("fma.rn.f32x2 %0, %1, %2, %3;" : "=l"(d) : "l"(a), "l"(b), "l"(d));
}
__device__ __forceinline__ u64 pack2(float x, float y){
    u64 r;
    asm("mov.b64 %0, {%1, %2};" : "=l"(r) : "r"(__float_as_uint(x)), "r"(__float_as_uint(y)));
    return r;
}
__device__ __forceinline__ float2 unpack2(u64 v){
    unsigned lo, hi;
    asm("mov.b64 {%0, %1}, %2;" : "=r"(lo), "=r"(hi) : "l"(v));
    return make_float2(__uint_as_float(lo), __uint_as_float(hi));
}

// ---------------- 0) transpose W_pe once ----------------
__global__ void k_wt(const float* __restrict__ Wpe){
    int idx = blockIdx.x*blockDim.x + threadIdx.x;
    if (idx < 768*96){
        int k = idx/96, d = idx%96;
        g_WpeT[idx] = Wpe[d*768 + k];
    }
}

// ---------------- 1) fused 5x5 box blur + log contrast (smem tiles) ----------------
__global__ void k_blur(const float* __restrict__ x){
    __shared__ float in_s[36][37];
    __shared__ float hs[36][33];
    int tid = threadIdx.x;                   // 256
    int p = blockIdx.x / 144;                // plane = b*3 + c
    int t = blockIdx.x % 144;
    int y0 = (t/12)*32, x0 = (t%12)*32;
    const float* xp = x + (size_t)p*IMG*IMG;

    for (int idx=tid; idx<36*36; idx+=256){
        int r = idx/36, cc = idx%36;
        int yy = y0-2+r, xx = x0-2+cc;
        in_s[r][cc] = (yy>=0 && yy<IMG && xx>=0 && xx<IMG) ? xp[yy*IMG+xx] : 0.f;
    }
    __syncthreads();
    for (int idx=tid; idx<36*32; idx+=256){
        int r = idx/32, j = idx%32;
        hs[r][j] = in_s[r][j]+in_s[r][j+1]+in_s[r][j+2]+in_s[r][j+3]+in_s[r][j+4];
    }
    __syncthreads();
    int b = p/3, c = p%3;
    for (int idx=tid; idx<32*32; idx+=256){
        int r = idx/32, j = idx%32;
        float bl = (hs[r][j]+hs[r+1][j]+hs[r+2][j]+hs[r+3][j]+hs[r+4][j])*(1.f/25.f);
        float xv = in_s[r+2][j+2];
        float v  = __logf(1.f + fmaxf(xv,0.f)) - __logf(1.f + fmaxf(bl,0.f));
        int yy = y0+r, xx = x0+j;
        int gp  = b*NT + (yy>>4)*HP + (xx>>4);
        int col = c*256 + (yy&15)*16 + (xx&15);
        g_xl[gp*768 + col] = v;
    }
}

// ---------------- 2) patch embed GEMM: [36864 x 768] @ [768 x 96] ----------------
// 256 threads, 128 rows x 96 cols, thread tile 8 rows x 3 col-pairs
__global__ void __launch_bounds__(256,2) k_patch(const float* __restrict__ bpe){
    __shared__ float As[128*33];
    __shared__ float Bs[32*96];
    __shared__ float bps[96];
    int tid = threadIdx.x;
    int tx = tid & 15, ty = tid >> 4;        // tx 0..15 (col-pairs), ty 0..15 (rows)
    int rowbase = blockIdx.x * 128;

    if (tid < 96) bps[tid] = bpe[tid];

    const float4* Xg = reinterpret_cast<const float4*>(g_xl);
    const float4* Wg = reinterpret_cast<const float4*>(g_WpeT);

    u64 acc[8][3];
    #pragma unroll
    for (int i=0;i<8;i++){ acc[i][0]=0ull; acc[i][1]=0ull; acc[i][2]=0ull; }

    for (int kc=0; kc<24; kc++){
        __syncthreads();
        #pragma unroll
        for (int r=0;r<4;r++){
            int idx = tid + 256*r;            // < 1024
            int row = idx >> 3, c4 = idx & 7;
            float4 v = Xg[(rowbase+row)*192 + kc*8 + c4];
            float* p = &As[row*33 + c4*4];
            p[0]=v.x; p[1]=v.y; p[2]=v.z; p[3]=v.w;
        }
        #pragma unroll
        for (int r=0;r<3;r++){
            int idx = tid + 256*r;            // < 768 float4s = 32 k-rows x 96 floats
            reinterpret_cast<float4*>(Bs)[idx] = Wg[kc*768 + idx];
        }
        __syncthreads();
        #pragma unroll
        for (int kk=0;kk<32;kk++){
            const u64* bp = reinterpret_cast<const u64*>(&Bs[kk*96 + tx*6]);
            u64 b0=bp[0], b1=bp[1], b2=bp[2];
            #pragma unroll
            for (int i=0;i<8;i++){
                float a = As[(ty + 16*i)*33 + kk];
                u64 ap = pack2(a,a);
                ffma2(acc[i][0],ap,b0);
                ffma2(acc[i][1],ap,b1);
                ffma2(acc[i][2],ap,b2);
            }
        }
    }
    #pragma unroll
    for (int i=0;i<8;i++){
        int row = rowbase + ty + 16*i;
        #pragma unroll
        for (int j=0;j<3;j++){
            float2 v = unpack2(acc[i][j]);
            int c = tx*6 + 2*j;
            g_tokens[row*96 + c]   = v.x + bps[c];
            g_tokens[row*96 + c+1] = v.y + bps[c+1];
        }
    }
}

// ---------------- 3) row GEMM with fused LN + epilogues ----------------
// MODE 0: raw tokens -> vis ; LN(dn) written back ; gate = sigmoid(LN @ W_gate + b)
// MODE 1: LN(ln)(tokens) @ W_in (192 cols) ; cols<96 -> g_xin ; cols>=96 -> g_zg = silu(z)*vis
// MODE 2: g_yg @ W_out ; tokens += out * gate
// W stride == COLS in all modes.
template<int MODE, int ROWS, int COLS, int TX, int TY, int TR>
__global__ void __launch_bounds__(256,2) k_gemm(const float* __restrict__ W,
                          const float* __restrict__ lng, const float* __restrict__ lnb,
                          const float* __restrict__ Wvis, const float* __restrict__ bvis,
                          const float* __restrict__ bgate){
    __shared__ float As[ROWS*97];
    __shared__ float Bs[16*COLS];
    __shared__ float sg[96], sb[96], sv[96];
    int tid = threadIdx.x;
    int tx = tid % TX, ty = tid / TX;
    int rowbase = blockIdx.x * ROWS;

    const float* Asrc = (MODE==2) ? g_yg : g_tokens;
    const float4* Ag = reinterpret_cast<const float4*>(Asrc + rowbase*96);
    for (int idx=tid; idx<ROWS*24; idx+=256){
        int row = idx/24, c4 = idx%24;
        float4 v = Ag[idx];
        float* p = &As[row*97 + c4*4];
        p[0]=v.x; p[1]=v.y; p[2]=v.z; p[3]=v.w;
    }
    if (MODE != 2 && tid < 96){
        sg[tid]=lng[tid]; sb[tid]=lnb[tid];
        if (MODE==0) sv[tid]=Wvis[tid];
    }
    __syncthreads();

    if (MODE != 2){
        // one thread per row: LN stats + normalize, no shuffles, conflict-free (pitch 97)
        if (tid < ROWS){
            float* ar = &As[tid*97];
            float s=0.f, q=0.f, vd=0.f;
            #pragma unroll 8
            for (int k=0;k<96;k++){
                float v = ar[k];
                s += v; q = fmaf(v,v,q);
                if (MODE==0) vd = fmaf(v, sv[k], vd);
            }
            float m  = s*(1.f/96.f);
            float var = fmaf(-m, m, q*(1.f/96.f));
            float rs = rsqrtf(var + 1e-5f);
            if (MODE==0) g_vis[rowbase+tid] = sigm_(vd + bvis[0]);
            #pragma unroll 8
            for (int k=0;k<96;k++){
                ar[k] = fmaf((ar[k]-m)*rs, sg[k], sb[k]);
            }
        }
        __syncthreads();
        if (MODE==0){
            float4* tdst = reinterpret_cast<float4*>(g_tokens + rowbase*96);
            for (int idx=tid; idx<ROWS*24; idx+=256){
                int row = idx/24, c4 = idx%24;
                const float* p = &As[row*97 + c4*4];
                tdst[idx] = make_float4(p[0],p[1],p[2],p[3]);
            }
        }
    }

    u64 acc[TR][3];
    #pragma unroll
    for (int i=0;i<TR;i++){ acc[i][0]=0ull; acc[i][1]=0ull; acc[i][2]=0ull; }

    for (int kc=0;kc<6;kc++){
        __syncthreads();
        for (int idx=tid; idx<16*(COLS/4); idx+=256){
            reinterpret_cast<float4*>(Bs)[idx] =
                *reinterpret_cast<const float4*>(W + kc*16*COLS + idx*4);
        }
        __syncthreads();
        #pragma unroll
        for (int kk=0;kk<16;kk++){
            int k = kc*16 + kk;
            const u64* bp = reinterpret_cast<const u64*>(&Bs[kk*COLS + tx*6]);
            u64 b0=bp[0], b1=bp[1], b2=bp[2];
            #pragma unroll
            for (int i=0;i<TR;i++){
                float a = As[(ty + TY*i)*97 + k];
                u64 ap = pack2(a,a);
                ffma2(acc[i][0],ap,b0);
                ffma2(acc[i][1],ap,b1);
                ffma2(acc[i][2],ap,b2);
            }
        }
    }

    #pragma unroll
    for (int i=0;i<TR;i++){
        int row = rowbase + ty + TY*i;
        float visr = 0.f;
        if (MODE==1 && tx >= TX/2) visr = g_vis[row];
        #pragma unroll
        for (int j=0;j<3;j++){
            float2 v = unpack2(acc[i][j]);
            int c = tx*6 + 2*j;
            if (MODE == 0){
                g_gate[row*96 + c]   = sigm_(v.x + bgate[c]);
                g_gate[row*96 + c+1] = sigm_(v.y + bgate[c+1]);
            } else if (MODE == 1){
                if (c < 96){
                    g_xin[row*96 + c]   = v.x;
                    g_xin[row*96 + c+1] = v.y;
                } else {
                    g_zg[row*96 + c-96]  = silu_(v.x)*visr;
                    g_zg[row*96 + c-95]  = silu_(v.y)*visr;
                }
            } else {
                g_tokens[row*96 + c]   += v.x * g_gate[row*96 + c];
                g_tokens[row*96 + c+1] += v.y * g_gate[row*96 + c+1];
            }
        }
    }
}

// ---------------- 4) fused conv1d+silu + proj + dt + meta pack ----------------
__global__ void k_cpd(const float* __restrict__ cw,
                      const float* __restrict__ Wx, const float* __restrict__ Wdt,
                      const float* __restrict__ bdt, const float* __restrict__ Dp){
    __shared__ float xin_s[34*97];
    __shared__ float xs_s[32*97];
    __shared__ float Wxs[96*38];
    __shared__ float pr[32*8];
    __shared__ float cws[288];
    __shared__ float wdts[6*96];
    __shared__ float dps[96];
    __shared__ float bdts[96];
    int tid = threadIdx.x;                   // 128
    int tb  = blockIdx.x * 32;
    int tt0 = tb % NT;

    for (int idx=tid; idx<34*96; idx+=128){
        int r = idx/96, d = idx%96;
        int t = tt0 - 2 + r;
        xin_s[r*97+d] = (t >= 0) ? g_xin[(tb - tt0 + t)*96 + d] : 0.f;
    }
    for (int idx=tid; idx<96*38; idx+=128) Wxs[idx] = Wx[idx];
    for (int idx=tid; idx<6*96;  idx+=128) wdts[idx] = Wdt[idx];
    if (tid < 96){
        cws[tid] = cw[tid*3+0]; cws[96+tid] = cw[tid*3+1]; cws[192+tid] = cw[tid*3+2];
        dps[tid] = Dp[tid]; bdts[tid] = bdt[tid];
    }
    __syncthreads();

    // conv + silu
    for (int idx=tid; idx<32*96; idx+=128){
        int l = idx/96, d = idx%96;
        float v = xin_s[l*97+d]*cws[d] + xin_s[(l+1)*97+d]*cws[96+d] + xin_s[(l+2)*97+d]*cws[192+d];
        xs_s[l*97+d] = silu_(v);
    }
    __syncthreads();

    // proj: [32 x 96] @ [96 x 38] with token-pair FFMA2
    {
        int tp = tid & 15;                   // token pair
        int jg = tid >> 4;                   // 0..7
        u64 acc5[5] = {0ull,0ull,0ull,0ull,0ull};
        const float* x0 = &xs_s[(2*tp)*97];
        const float* x1 = x0 + 97;
        #pragma unroll 4
        for (int k=0;k<96;k++){
            u64 ap = pack2(x0[k], x1[k]);
            #pragma unroll
            for (int q=0;q<5;q++){
                int j = jg + 8*q;
                if (j < 38){
                    float w = Wxs[k*38 + j];
                    ffma2(acc5[q], ap, pack2(w,w));
                }
            }
        }
        #pragma unroll
        for (int q=0;q<5;q++){
            int j = jg + 8*q;
            if (j < 38){
                float2 v = unpack2(acc5[q]);
                if (j < 6){
                    pr[(2*tp)*8 + j]   = v.x;
                    pr[(2*tp+1)*8 + j] = v.y;
                } else {
                    g_bc[(tb+2*tp)*32   + (j-6)] = v.x;
                    g_bc[(tb+2*tp+1)*32 + (j-6)] = v.y;
                }
            }
        }
    }
    __syncthreads();

    // dt = softplus(dt_raw @ W_dt + b_dt) + meta pack
    for (int idx=tid; idx<32*96; idx+=128){
        int l = idx/96, d = idx%96;
        float a = bdts[d];
        #pragma unroll
        for (int r=0;r<6;r++) a = fmaf(pr[l*8+r], wdts[r*96+d], a);
        float dt = softplus_(a);
        float xs = xs_s[l*97+d];
        float zg = g_zg[(tb+l)*96 + d];
        float4 m;
        m.x = dt;
        m.y = dt*xs;
        m.z = dps[d]*xs*zg;
        m.w = zg;
        g_meta[(tb+l)*96 + d] = m;
    }
}

// ---------------- 5) selective scan: 8 lanes/d, 2 states/lane, 4 d per warp ----------------
__global__ void k_scan(const float* __restrict__ Alog){
    int b    = blockIdx.x / 6;
    int dgrp = blockIdx.x % 6;
    int w    = threadIdx.x >> 5;
    int lane = threadIdx.x & 31;
    int g    = lane >> 3;
    int sl   = lane & 7;
    int s0   = 2*sl;
    int d    = dgrp*16 + w*4 + g;

    float A0 = -__expf(Alog[d*DS + s0]);
    float A1 = -__expf(Alog[d*DS + s0 + 1]);
    float h0 = 0.f, h1 = 0.f;

    const float4* mp  = g_meta + b*NT*DI + d;
    const float*  bcp = g_bc   + b*NT*32;
    float*        yo  = g_yg   + b*NT*DI + d;

    #pragma unroll 4
    for (int t=0; t<NT; t++){
        float4 m = mp[t*DI];
        float2 Bv = *reinterpret_cast<const float2*>(bcp + t*32 + s0);
        float2 Cv = *reinterpret_cast<const float2*>(bcp + t*32 + 16 + s0);
        float e0 = __expf(m.x * A0);
        float e1 = __expf(m.x * A1);
        h0 = fmaf(e0, h0, m.y * Bv.x);
        h1 = fmaf(e1, h1, m.y * Bv.y);
        float yp = fmaf(h1, Cv.y, h0 * Cv.x);
        yp += __shfl_xor_sync(0xffffffffu, yp, 1);
        yp += __shfl_xor_sync(0xffffffffu, yp, 2);
        yp += __shfl_xor_sync(0xffffffffu, yp, 4);
        if (sl == 0){
            yo[t*DI] = fmaf(yp, m.w, m.z);
        }
    }
}

// ---------------- 6) heads: depthwise 3x3 + BN + silu + three matvecs ----------------
__global__ void k_final(const float* __restrict__ hd,
                        const float* __restrict__ bng, const float* __restrict__ bnb,
                        const float* __restrict__ bnm, const float* __restrict__ bnv,
                        const float* __restrict__ Wheat, const float* __restrict__ bheat,
                        const float* __restrict__ Woff,  const float* __restrict__ boff,
                        const float* __restrict__ Wsize, const float* __restrict__ bsize,
                        float* __restrict__ out){
    __shared__ float fr[3][HP][97];
    __shared__ float gs[HP][97];
    int tid = threadIdx.x;
    int b = blockIdx.x / HP;
    int h = blockIdx.x % HP;

    for (int idx=tid; idx<3*HP*96; idx+=128){
        int r = idx/(HP*96);
        int rem = idx - r*HP*96;
        int wq = rem/96, d = rem%96;
        int hh = h - 1 + r;
        fr[r][wq][d] = (hh>=0 && hh<HP) ? g_tokens[(b*NT + hh*HP + wq)*DM + d] : 0.f;
    }
    __syncthreads();

    for (int idx=tid; idx<HP*96; idx+=128){
        int wq = idx/96, d = idx%96;
        float a = 0.f;
        #pragma unroll
        for (int i=0;i<3;i++)
            #pragma unroll
            for (int j=0;j<3;j++){
                int ww = wq - 1 + j;
                if (ww>=0 && ww<HP) a = fmaf(fr[i][ww][d], hd[d*9 + i*3 + j], a);
            }
        a = (a - bnm[d]) * rsqrtf(bnv[d] + 1e-5f);
        gs[wq][d] = silu_(a*bng[d] + bnb[d]);
    }
    __syncthreads();

    const int HEAT_OFF = 0;
    const int OFF_OFF  = NB*5*NT;
    const int SIZE_OFF = OFF_OFF + NB*2*NT;
    for (int idx=tid; idx<HP*9; idx+=128){
        int wq = idx/9, o = idx%9;
        if (o < 5){
            float a = bheat[o];
            #pragma unroll 8
            for (int d=0; d<96; d++) a = fmaf(gs[wq][d], Wheat[o*96+d], a);
            out[HEAT_OFF + ((b*5+o)*HP + h)*HP + wq] = a;
        } else if (o < 7){
            int oo = o-5;
            float a = boff[oo];
            #pragma unroll 8
            for (int d=0; d<96; d++) a = fmaf(fr[1][wq][d], Woff[oo*96+d], a);
            out[OFF_OFF + ((b*2+oo)*HP + h)*HP + wq] = a;
        } else {
            int oo = o-7;
            float a = bsize[oo];
            #pragma unroll 8
            for (int d=0; d<96; d++) a = fmaf(fr[1][wq][d], Wsize[oo*96+d], a);
            out[SIZE_OFF + ((b*2+oo)*HP + h)*HP + wq] = a;
        }
    }
}

// ---------------- launch ----------------
extern "C" void kernel_launch(void* const* d_in, const int* in_sizes, int n_in,
                              void* d_out, int out_size){
    const float* x      = (const float*)d_in[0];
    const float* W_pe   = (const float*)d_in[1];
    const float* b_pe   = (const float*)d_in[2];
    const float* W_vis  = (const float*)d_in[3];
    const float* b_vis  = (const float*)d_in[4];
    const float* dn_g   = (const float*)d_in[5];
    const float* dn_b   = (const float*)d_in[6];
    const float* W_gate = (const float*)d_in[7];
    const float* b_gate = (const float*)d_in[8];
    const float* ln_g   = (const float*)d_in[9];
    const float* ln_b   = (const float*)d_in[10];
    const float* W_in   = (const float*)d_in[11];
    const float* conv_w = (const float*)d_in[12];
    const float* W_xprj = (const float*)d_in[13];
    const float* W_dt   = (const float*)d_in[14];
    const float* b_dt   = (const float*)d_in[15];
    const float* A_log  = (const float*)d_in[16];
    const float* Dp     = (const float*)d_in[17];
    const float* W_out  = (const float*)d_in[18];
    const float* hd_dw  = (const float*)d_in[19];
    const float* bn_g   = (const float*)d_in[20];
    const float* bn_b   = (const float*)d_in[21];
    const float* bn_m   = (const float*)d_in[22];
    const float* bn_v   = (const float*)d_in[23];
    const float* W_heat = (const float*)d_in[24];
    const float* b_heat = (const float*)d_in[25];
    const float* W_off  = (const float*)d_in[26];
    const float* b_off  = (const float*)d_in[27];
    const float* W_size = (const float*)d_in[28];
    const float* b_size = (const float*)d_in[29];
    float* out = (float*)d_out;

    k_wt<<<(768*96+255)/256, 256>>>(W_pe);
    k_blur<<<192*144, 256>>>(x);
    k_patch<<<NR/128, 256>>>(b_pe);

    // MODE 0: 96 rows x 96 cols, TX=16, TY=16, TR=6
    k_gemm<0,96,96,16,16,6><<<NR/96, 256>>>(W_gate, dn_g, dn_b, W_vis, b_vis, b_gate);

    for (int rep=0; rep<4; rep++){
        // MODE 1: 64 rows x 192 cols, TX=32, TY=8, TR=8
        k_gemm<1,64,192,32,8,8><<<NR/64, 256>>>(W_in, ln_g, ln_b, nullptr, nullptr, nullptr);
        k_cpd<<<NR/32, 128>>>(conv_w, W_xprj, W_dt, b_dt, Dp);
        k_scan<<<NB*6, 128>>>(A_log);
        // MODE 2: 96 rows x 96 cols
        k_gemm<2,96,96,16,16,6><<<NR/96, 256>>>(W_out, nullptr, nullptr, nullptr, nullptr, nullptr);
    }

    k_final<<<NB*HP, 128>>>(hd_dw, bn_g, bn_b, bn_m, bn_v,
                            W_heat, b_heat, W_off, b_off, W_size, b_size, out);
}

// round 7
// speedup vs baseline: 1.0724x; 1.0724x over previous
#include <cuda_runtime.h>
#include <math.h>

#define NB   64
#define IMG  384
#define CIN  3
#define PS   16
#define DM   96
#define DS   16
#define DI   96
#define HP   24
#define NT   576
#define NR   (NB*NT)          // 36864 token rows
#define NPIX (NB*CIN*IMG*IMG) // 28311552

// ---------------- scratch (device globals; no allocs allowed) ----------------
static __device__ float  g_xl[NPIX];        // preprocessed image, PATCH-MAJOR [gp][768]
static __device__ float  g_WpeT[768*96];    // transposed patch weights [k][d]
static __device__ float  g_tokens[NR*DM];
static __device__ float  g_vis[NR];
static __device__ float  g_gate[NR*DM];
static __device__ float  g_xin[NR*DI];      // pre-conv x branch
static __device__ float  g_zg[NR*DI];       // silu(z)*vis
static __device__ float  g_bc[NR*32];       // B(16) | C(16)
static __device__ float4 g_meta[NR*DI];     // {dt, dt*xs, D*xs*zg, zg}
static __device__ float  g_yg[NR*DI];

__device__ __forceinline__ float sigm_(float x){ return 1.f/(1.f+__expf(-x)); }
__device__ __forceinline__ float silu_(float x){ return x/(1.f+__expf(-x)); }
__device__ __forceinline__ float softplus_(float x){ return (x>20.f)? x : __logf(1.f+__expf(x)); }

// ---- packed fp32x2 helpers (Blackwell FFMA2 path, PTX-only) ----
typedef unsigned long long u64;
__device__ __forceinline__ void ffma2(u64 &d, u64 a, u64 b){
    asm("fma.rn.f32x2 %0, %1, %2, %3;" : "=l"(d) : "l"(a), "l"(b), "l"(d));
}
__device__ __forceinline__ u64 pack2(float x, float y){
    u64 r;
    asm("mov.b64 %0, {%1, %2};" : "=l"(r) : "r"(__float_as_uint(x)), "r"(__float_as_uint(y)));
    return r;
}
__device__ __forceinline__ float2 unpack2(u64 v){
    unsigned lo, hi;
    asm("mov.b64 {%0, %1}, %2;" : "=r"(lo), "=r"(hi) : "l"(v));
    return make_float2(__uint_as_float(lo), __uint_as_float(hi));
}

// ---------------- 0) transpose W_pe once ----------------
__global__ void k_wt(const float* __restrict__ Wpe){
    int idx = blockIdx.x*blockDim.x + threadIdx.x;
    if (idx < 768*96){
        int k = idx/96, d = idx%96;
        g_WpeT[idx] = Wpe[d*768 + k];
    }
}

// ---------------- 1) fused 5x5 box blur + log contrast (smem tiles) ----------------
__global__ void k_blur(const float* __restrict__ x){
    __shared__ float in_s[36][37];
    __shared__ float hs[36][33];
    int tid = threadIdx.x;                   // 256
    int p = blockIdx.x / 144;                // plane = b*3 + c
    int t = blockIdx.x % 144;
    int y0 = (t/12)*32, x0 = (t%12)*32;
    const float* xp = x + (size_t)p*IMG*IMG;

    for (int idx=tid; idx<36*36; idx+=256){
        int r = idx/36, cc = idx%36;
        int yy = y0-2+r, xx = x0-2+cc;
        in_s[r][cc] = (yy>=0 && yy<IMG && xx>=0 && xx<IMG) ? xp[yy*IMG+xx] : 0.f;
    }
    __syncthreads();
    for (int idx=tid; idx<36*32; idx+=256){
        int r = idx/32, j = idx%32;
        hs[r][j] = in_s[r][j]+in_s[r][j+1]+in_s[r][j+2]+in_s[r][j+3]+in_s[r][j+4];
    }
    __syncthreads();
    int b = p/3, c = p%3;
    for (int idx=tid; idx<32*32; idx+=256){
        int r = idx/32, j = idx%32;
        float bl = (hs[r][j]+hs[r+1][j]+hs[r+2][j]+hs[r+3][j]+hs[r+4][j])*(1.f/25.f);
        float xv = in_s[r+2][j+2];
        float v  = __logf(1.f + fmaxf(xv,0.f)) - __logf(1.f + fmaxf(bl,0.f));
        int yy = y0+r, xx = x0+j;
        int gp  = b*NT + (yy>>4)*HP + (xx>>4);
        int col = c*256 + (yy&15)*16 + (xx&15);
        g_xl[gp*768 + col] = v;
    }
}

// ---------------- 2) patch embed GEMM (R2-proven): [36864 x 768] @ [768 x 96] ----------------
// 128 threads, 64 rows x 96 cols per block, thread tile 8r x 3 col-pairs
__global__ void k_patch(const float* __restrict__ bpe){
    __shared__ __align__(16) float As[64][64];
    __shared__ __align__(16) float Bs[64][96];
    int tid = threadIdx.x;
    int tx = tid & 15, ty = tid >> 4;        // tx 0..15, ty 0..7
    int rowbase = blockIdx.x * 64;
    int tx6 = tx*6;

    u64 acc[8][3];
    #pragma unroll
    for (int i=0;i<8;i++){ acc[i][0]=0ull; acc[i][1]=0ull; acc[i][2]=0ull; }

    const float4* Xg = reinterpret_cast<const float4*>(g_xl);
    const float4* Wg = reinterpret_cast<const float4*>(g_WpeT);
    float4* As4 = reinterpret_cast<float4*>(&As[0][0]);
    float4* Bs4 = reinterpret_cast<float4*>(&Bs[0][0]);

    for (int kc=0; kc<12; kc++){
        #pragma unroll
        for (int r=0;r<8;r++){
            int idx = tid + 128*r;           // < 1024
            int row = idx >> 4, c4 = idx & 15;
            As4[idx] = Xg[(rowbase+row)*192 + kc*16 + c4];
        }
        #pragma unroll
        for (int r=0;r<12;r++){
            int idx = tid + 128*r;           // < 1536
            int kk = idx/24, c4 = idx%24;
            Bs4[idx] = Wg[(kc*64+kk)*24 + c4];
        }
        __syncthreads();
        #pragma unroll 8
        for (int kk=0;kk<64;kk++){
            const u64* bp = reinterpret_cast<const u64*>(&Bs[kk][tx6]);
            u64 b0 = bp[0], b1 = bp[1], b2 = bp[2];
            #pragma unroll
            for (int i=0;i<8;i++){
                float a = As[ty + 8*i][kk];
                u64 ap = pack2(a, a);
                ffma2(acc[i][0], ap, b0);
                ffma2(acc[i][1], ap, b1);
                ffma2(acc[i][2], ap, b2);
            }
        }
        __syncthreads();
    }
    #pragma unroll
    for (int i=0;i<8;i++){
        int row = rowbase + ty + 8*i;
        #pragma unroll
        for (int j=0;j<3;j++){
            float2 v = unpack2(acc[i][j]);
            int c = tx6 + 2*j;
            g_tokens[row*DM + c]   = v.x + bpe[c];
            g_tokens[row*DM + c+1] = v.y + bpe[c+1];
        }
    }
}

// ---------------- 3) row GEMM with fused LN + epilogues (R2-proven mainloop) ----------------
// MODE 0: raw tokens -> vis ; LN(dn) written back ; gate = sigmoid(LN @ W_gate + b)
// MODE 1: LN(ln)(tokens) @ W_in ; both 96-col halves in one block (cb=0 -> g_xin, cb=96 -> g_zg)
// MODE 2: g_yg @ W_out ; tokens += out * gate
template<int MODE>
__global__ void k_rowgemm(const float* __restrict__ W, int wstride,
                          const float* __restrict__ lng, const float* __restrict__ lnb,
                          const float* __restrict__ Wvis, const float* __restrict__ bvis,
                          const float* __restrict__ bgate){
    __shared__ __align__(16) float As[64][96];
    __shared__ __align__(16) float Bs[32][96];
    int tid = threadIdx.x;
    int tx = tid & 15, ty = tid >> 4;
    int rowbase = blockIdx.x * 64;
    int tx6 = tx*6;

    const float* Asrc = (MODE==2) ? g_yg : g_tokens;
    const float4* Ag = reinterpret_cast<const float4*>(Asrc + rowbase*96);
    float4* As4 = reinterpret_cast<float4*>(&As[0][0]);
    float4* Bs4 = reinterpret_cast<float4*>(&Bs[0][0]);
    #pragma unroll
    for (int r=0;r<12;r++) As4[tid + 128*r] = Ag[tid + 128*r];
    __syncthreads();

    if (MODE != 2){
        int warp = tid >> 5, lane = tid & 31;
        for (int rr=0; rr<16; rr++){
            int row = warp*16 + rr;
            float v0 = As[row][lane], v1 = As[row][lane+32], v2 = As[row][lane+64];
            float s = v0+v1+v2;
            #pragma unroll
            for (int o=16;o;o>>=1) s += __shfl_xor_sync(0xffffffffu, s, o);
            float m = s*(1.f/96.f);
            float d0=v0-m, d1=v1-m, d2=v2-m;
            float q = d0*d0 + d1*d1 + d2*d2;
            #pragma unroll
            for (int o=16;o;o>>=1) q += __shfl_xor_sync(0xffffffffu, q, o);
            float rs = rsqrtf(q*(1.f/96.f) + 1e-5f);
            if (MODE == 0){
                float vd = v0*Wvis[lane] + v1*Wvis[lane+32] + v2*Wvis[lane+64];
                #pragma unroll
                for (int o=16;o;o>>=1) vd += __shfl_xor_sync(0xffffffffu, vd, o);
                if (lane==0) g_vis[rowbase+row] = sigm_(vd + bvis[0]);
            }
            float n0 = d0*rs*lng[lane]    + lnb[lane];
            float n1 = d1*rs*lng[lane+32] + lnb[lane+32];
            float n2 = d2*rs*lng[lane+64] + lnb[lane+64];
            As[row][lane]=n0; As[row][lane+32]=n1; As[row][lane+64]=n2;
            if (MODE == 0){
                float* tp = g_tokens + (rowbase+row)*96;
                tp[lane]=n0; tp[lane+32]=n1; tp[lane+64]=n2;
            }
        }
    }

    const int NHALF = (MODE==1) ? 2 : 1;
    for (int half=0; half<NHALF; half++){
        int cb = half*96;

        u64 acc[8][3];
        #pragma unroll
        for (int i=0;i<8;i++){ acc[i][0]=0ull; acc[i][1]=0ull; acc[i][2]=0ull; }

        for (int kc=0;kc<3;kc++){
            __syncthreads();
            #pragma unroll
            for (int r=0;r<6;r++){
                int idx = tid + 128*r;        // < 768
                int kk = idx/24, c4 = idx%24;
                Bs4[idx] = *reinterpret_cast<const float4*>(W + (kc*32+kk)*wstride + cb + c4*4);
            }
            __syncthreads();
            #pragma unroll 8
            for (int kk=0;kk<32;kk++){
                const u64* bp = reinterpret_cast<const u64*>(&Bs[kk][tx6]);
                u64 b0 = bp[0], b1 = bp[1], b2 = bp[2];
                int kidx = kc*32 + kk;
                #pragma unroll
                for (int i=0;i<8;i++){
                    float a = As[ty + 8*i][kidx];
                    u64 ap = pack2(a, a);
                    ffma2(acc[i][0], ap, b0);
                    ffma2(acc[i][1], ap, b1);
                    ffma2(acc[i][2], ap, b2);
                }
            }
        }

        #pragma unroll
        for (int i=0;i<8;i++){
            int row = rowbase + ty + 8*i;
            float visr = 0.f;
            if (MODE == 1 && half == 1) visr = g_vis[row];
            #pragma unroll
            for (int j=0;j<3;j++){
                float2 v = unpack2(acc[i][j]);
                int c = tx6 + 2*j;
                if (MODE == 0){
                    g_gate[row*96 + c]   = sigm_(v.x + bgate[c]);
                    g_gate[row*96 + c+1] = sigm_(v.y + bgate[c+1]);
                } else if (MODE == 1){
                    if (half == 0){
                        g_xin[row*96 + c]   = v.x;
                        g_xin[row*96 + c+1] = v.y;
                    } else {
                        g_zg[row*96 + c]   = silu_(v.x)*visr;
                        g_zg[row*96 + c+1] = silu_(v.y)*visr;
                    }
                } else {
                    g_tokens[row*96 + c]   += v.x * g_gate[row*96 + c];
                    g_tokens[row*96 + c+1] += v.y * g_gate[row*96 + c+1];
                }
            }
        }
    }
}

// ---------------- 4) fused conv1d+silu + proj + dt + meta pack ----------------
__global__ void k_cpd(const float* __restrict__ cw,
                      const float* __restrict__ Wx, const float* __restrict__ Wdt,
                      const float* __restrict__ bdt, const float* __restrict__ Dp){
    __shared__ float xin_s[34*97];
    __shared__ float xs_s[32*97];
    __shared__ float Wxs[96*38];
    __shared__ float pr[32*8];
    __shared__ float cws[288];
    __shared__ float wdts[6*96];
    __shared__ float dps[96];
    __shared__ float bdts[96];
    int tid = threadIdx.x;                   // 128
    int tb  = blockIdx.x * 32;
    int tt0 = tb % NT;

    for (int idx=tid; idx<34*96; idx+=128){
        int r = idx/96, d = idx%96;
        int t = tt0 - 2 + r;
        xin_s[r*97+d] = (t >= 0) ? g_xin[(tb - tt0 + t)*96 + d] : 0.f;
    }
    for (int idx=tid; idx<96*38; idx+=128) Wxs[idx] = Wx[idx];
    for (int idx=tid; idx<6*96;  idx+=128) wdts[idx] = Wdt[idx];
    if (tid < 96){
        cws[tid] = cw[tid*3+0]; cws[96+tid] = cw[tid*3+1]; cws[192+tid] = cw[tid*3+2];
        dps[tid] = Dp[tid]; bdts[tid] = bdt[tid];
    }
    __syncthreads();

    // conv + silu
    for (int idx=tid; idx<32*96; idx+=128){
        int l = idx/96, d = idx%96;
        float v = xin_s[l*97+d]*cws[d] + xin_s[(l+1)*97+d]*cws[96+d] + xin_s[(l+2)*97+d]*cws[192+d];
        xs_s[l*97+d] = silu_(v);
    }
    __syncthreads();

    // proj: [32 x 96] @ [96 x 38] with token-pair FFMA2
    {
        int tp = tid & 15;                   // token pair
        int jg = tid >> 4;                   // 0..7
        u64 acc5[5] = {0ull,0ull,0ull,0ull,0ull};
        const float* x0 = &xs_s[(2*tp)*97];
        const float* x1 = x0 + 97;
        #pragma unroll 4
        for (int k=0;k<96;k++){
            u64 ap = pack2(x0[k], x1[k]);
            #pragma unroll
            for (int q=0;q<5;q++){
                int j = jg + 8*q;
                if (j < 38){
                    float w = Wxs[k*38 + j];
                    ffma2(acc5[q], ap, pack2(w,w));
                }
            }
        }
        #pragma unroll
        for (int q=0;q<5;q++){
            int j = jg + 8*q;
            if (j < 38){
                float2 v = unpack2(acc5[q]);
                if (j < 6){
                    pr[(2*tp)*8 + j]   = v.x;
                    pr[(2*tp+1)*8 + j] = v.y;
                } else {
                    g_bc[(tb+2*tp)*32   + (j-6)] = v.x;
                    g_bc[(tb+2*tp+1)*32 + (j-6)] = v.y;
                }
            }
        }
    }
    __syncthreads();

    // dt = softplus(dt_raw @ W_dt + b_dt) + meta pack
    for (int idx=tid; idx<32*96; idx+=128){
        int l = idx/96, d = idx%96;
        float a = bdts[d];
        #pragma unroll
        for (int r=0;r<6;r++) a = fmaf(pr[l*8+r], wdts[r*96+d], a);
        float dt = softplus_(a);
        float xs = xs_s[l*97+d];
        float zg = g_zg[(tb+l)*96 + d];
        float4 m;
        m.x = dt;
        m.y = dt*xs;
        m.z = dps[d]*xs*zg;
        m.w = zg;
        g_meta[(tb+l)*96 + d] = m;
    }
}

// ---------------- 5) selective scan: 8 lanes/d, 2 states/lane, 4 d per warp ----------------
__global__ void k_scan(const float* __restrict__ Alog){
    int b    = blockIdx.x / 6;
    int dgrp = blockIdx.x % 6;
    int w    = threadIdx.x >> 5;
    int lane = threadIdx.x & 31;
    int g    = lane >> 3;
    int sl   = lane & 7;
    int s0   = 2*sl;
    int d    = dgrp*16 + w*4 + g;

    float A0 = -__expf(Alog[d*DS + s0]);
    float A1 = -__expf(Alog[d*DS + s0 + 1]);
    float h0 = 0.f, h1 = 0.f;

    const float4* mp  = g_meta + b*NT*DI + d;
    const float*  bcp = g_bc   + b*NT*32;
    float*        yo  = g_yg   + b*NT*DI + d;

    #pragma unroll 4
    for (int t=0; t<NT; t++){
        float4 m = mp[t*DI];
        float2 Bv = *reinterpret_cast<const float2*>(bcp + t*32 + s0);
        float2 Cv = *reinterpret_cast<const float2*>(bcp + t*32 + 16 + s0);
        float e0 = __expf(m.x * A0);
        float e1 = __expf(m.x * A1);
        h0 = fmaf(e0, h0, m.y * Bv.x);
        h1 = fmaf(e1, h1, m.y * Bv.y);
        float yp = fmaf(h1, Cv.y, h0 * Cv.x);
        yp += __shfl_xor_sync(0xffffffffu, yp, 1);
        yp += __shfl_xor_sync(0xffffffffu, yp, 2);
        yp += __shfl_xor_sync(0xffffffffu, yp, 4);
        if (sl == 0){
            yo[t*DI] = fmaf(yp, m.w, m.z);
        }
    }
}

// ---------------- 6) heads: depthwise 3x3 + BN + silu + three matvecs ----------------
__global__ void k_final(const float* __restrict__ hd,
                        const float* __restrict__ bng, const float* __restrict__ bnb,
                        const float* __restrict__ bnm, const float* __restrict__ bnv,
                        const float* __restrict__ Wheat, const float* __restrict__ bheat,
                        const float* __restrict__ Woff,  const float* __restrict__ boff,
                        const float* __restrict__ Wsize, const float* __restrict__ bsize,
                        float* __restrict__ out){
    __shared__ float fr[3][HP][97];
    __shared__ float gs[HP][97];
    int tid = threadIdx.x;
    int b = blockIdx.x / HP;
    int h = blockIdx.x % HP;

    for (int idx=tid; idx<3*HP*96; idx+=128){
        int r = idx/(HP*96);
        int rem = idx - r*HP*96;
        int wq = rem/96, d = rem%96;
        int hh = h - 1 + r;
        fr[r][wq][d] = (hh>=0 && hh<HP) ? g_tokens[(b*NT + hh*HP + wq)*DM + d] : 0.f;
    }
    __syncthreads();

    for (int idx=tid; idx<HP*96; idx+=128){
        int wq = idx/96, d = idx%96;
        float a = 0.f;
        #pragma unroll
        for (int i=0;i<3;i++)
            #pragma unroll
            for (int j=0;j<3;j++){
                int ww = wq - 1 + j;
                if (ww>=0 && ww<HP) a = fmaf(fr[i][ww][d], hd[d*9 + i*3 + j], a);
            }
        a = (a - bnm[d]) * rsqrtf(bnv[d] + 1e-5f);
        gs[wq][d] = silu_(a*bng[d] + bnb[d]);
    }
    __syncthreads();

    const int HEAT_OFF = 0;
    const int OFF_OFF  = NB*5*NT;
    const int SIZE_OFF = OFF_OFF + NB*2*NT;
    for (int idx=tid; idx<HP*9; idx+=128){
        int wq = idx/9, o = idx%9;
        if (o < 5){
            float a = bheat[o];
            #pragma unroll 8
            for (int d=0; d<96; d++) a = fmaf(gs[wq][d], Wheat[o*96+d], a);
            out[HEAT_OFF + ((b*5+o)*HP + h)*HP + wq] = a;
        } else if (o < 7){
            int oo = o-5;
            float a = boff[oo];
            #pragma unroll 8
            for (int d=0; d<96; d++) a = fmaf(fr[1][wq][d], Woff[oo*96+d], a);
            out[OFF_OFF + ((b*2+oo)*HP + h)*HP + wq] = a;
        } else {
            int oo = o-7;
            float a = bsize[oo];
            #pragma unroll 8
            for (int d=0; d<96; d++) a = fmaf(fr[1][wq][d], Wsize[oo*96+d], a);
            out[SIZE_OFF + ((b*2+oo)*HP + h)*HP + wq] = a;
        }
    }
}

// ---------------- launch ----------------
extern "C" void kernel_launch(void* const* d_in, const int* in_sizes, int n_in,
                              void* d_out, int out_size){
    const float* x      = (const float*)d_in[0];
    const float* W_pe   = (const float*)d_in[1];
    const float* b_pe   = (const float*)d_in[2];
    const float* W_vis  = (const float*)d_in[3];
    const float* b_vis  = (const float*)d_in[4];
    const float* dn_g   = (const float*)d_in[5];
    const float* dn_b   = (const float*)d_in[6];
    const float* W_gate = (const float*)d_in[7];
    const float* b_gate = (const float*)d_in[8];
    const float* ln_g   = (const float*)d_in[9];
    const float* ln_b   = (const float*)d_in[10];
    const float* W_in   = (const float*)d_in[11];
    const float* conv_w = (const float*)d_in[12];
    const float* W_xprj = (const float*)d_in[13];
    const float* W_dt   = (const float*)d_in[14];
    const float* b_dt   = (const float*)d_in[15];
    const float* A_log  = (const float*)d_in[16];
    const float* Dp     = (const float*)d_in[17];
    const float* W_out  = (const float*)d_in[18];
    const float* hd_dw  = (const float*)d_in[19];
    const float* bn_g   = (const float*)d_in[20];
    const float* bn_b   = (const float*)d_in[21];
    const float* bn_m   = (const float*)d_in[22];
    const float* bn_v   = (const float*)d_in[23];
    const float* W_heat = (const float*)d_in[24];
    const float* b_heat = (const float*)d_in[25];
    const float* W_off  = (const float*)d_in[26];
    const float* b_off  = (const float*)d_in[27];
    const float* W_size = (const float*)d_in[28];
    const float* b_size = (const float*)d_in[29];
    float* out = (float*)d_out;

    k_wt<<<(768*96+255)/256, 256>>>(W_pe);
    k_blur<<<192*144, 256>>>(x);
    k_patch<<<NR/64, 128>>>(b_pe);

    k_rowgemm<0><<<NR/64, 128>>>(W_gate, 96, dn_g, dn_b, W_vis, b_vis, b_gate);

    for (int rep=0; rep<4; rep++){
        k_rowgemm<1><<<NR/64, 128>>>(W_in, 192, ln_g, ln_b, nullptr, nullptr, nullptr);
        k_cpd<<<NR/32, 128>>>(conv_w, W_xprj, W_dt, b_dt, Dp);
        k_scan<<<NB*6, 128>>>(A_log);
        k_rowgemm<2><<<NR/64, 128>>>(W_out, 96, nullptr, nullptr, nullptr, nullptr, nullptr);
    }

    k_final<<<NB*HP, 128>>>(hd_dw, bn_g, bn_b, bn_m, bn_v,
                            W_heat, b_heat, W_off, b_off, W_size, b_size, out);
}